// round 13
// baseline (speedup 1.0000x reference)
#include <cuda_runtime.h>
#include <cuda_bf16.h>
#include <math_constants.h>

// ---------------------------------------------------------------------------
// CNNTest: graph conv (1->32) -> graph conv (32->64) -> FC(64->512) -> softmax
// V = 100000, N = 32 neighbors.
//
// R12 (resubmitted R13 after infra timeout): f1 and h2 stored as bf16.
//   - k_h2 is L2-BW bound (400MB of 128B-row gathers); bf16 rows (64B) halve
//     L2 traffic and L1 wavefronts -> ~2x on k_h2.
//   - h2 was converted to bf16 in k_out anyway; storing bf16 is precision-free
//     and removes the convert from the panel build.
// k_out stays on bf16 tensor cores (R11: mma.sync.m16n8k16, 205.8us total).
// ---------------------------------------------------------------------------

#define V_MAX 100352
#define NNB   32

__device__ float          g_h  [V_MAX];
__device__ unsigned short g_f1b[V_MAX * 32];   // bf16 bits
__device__ unsigned short g_h2b[V_MAX * 32];   // bf16 bits
__device__ unsigned g_Wcb2[6 * 64 * 2 * 32];   // [kstep][ntile][b0/b1][lane] bf16x2
__device__ float g_bc[512];

// --------------------------- K1: first graph conv (to scalar h) ------------
__global__ void k_h(const float* __restrict__ vp, const int* __restrict__ nb1,
                    const float* __restrict__ wv1, const float* __restrict__ bv1,
                    int V) {
    int t = blockIdx.x * blockDim.x + threadIdx.x;
    int v = t >> 5;
    int j = t & 31;
    if (v >= V) return;
    float w0 = wv1[0], w1c = wv1[1], w2c = wv1[2], b = bv1[0];

    int   idx = nb1[v * NNB + j];
    float g   = vp[idx];
    float gm  = __shfl_up_sync(0xffffffffu, g, 1);
    float gp  = __shfl_down_sync(0xffffffffu, g, 1);
    if (j == 0)  gm = 0.f;
    if (j == 31) gp = 0.f;
    float c = fmaf(w0, gm, fmaf(w1c, g, fmaf(w2c, gp, b)));
    float r = fmaxf(c, 0.f);
#pragma unroll
    for (int s = 16; s > 0; s >>= 1)
        r += __shfl_xor_sync(0xffffffffu, r, s);
    if (j == 0) g_h[v] = r * (1.f / 32.f);
}

// --------------------------- K2: vertex conv 1 -> 32 channels (bf16 out) ---
__global__ void k_f1(const float* __restrict__ w1, const float* __restrict__ b1,
                     int V) {
    int t = blockIdx.x * blockDim.x + threadIdx.x;
    if (t >= V * 32) return;
    int v = t >> 5;
    int o = t & 31;
    float hm = (v > 0)     ? g_h[v - 1] : 0.f;
    float h0 = g_h[v];
    float hp = (v < V - 1) ? g_h[v + 1] : 0.f;
    float f = fmaf(hm, w1[o * 3 + 0],
              fmaf(h0, w1[o * 3 + 1],
              fmaf(hp, w1[o * 3 + 2], b1[o])));
    g_f1b[t] = __bfloat16_as_ushort(__float2bfloat16(f));
}

// --------------------------- K3: second graph conv (neighbor axis) ---------
// One warp per vertex, lane = channel. Gather rows are now 64B bf16 ->
// half the L2 traffic / L1 wavefronts vs fp32.
__global__ void k_h2(const int* __restrict__ nb2,
                     const float* __restrict__ wv2, const float* __restrict__ bv2,
                     int V) {
    int t = blockIdx.x * blockDim.x + threadIdx.x;
    int v = t >> 5;
    int c = t & 31;
    if (v >= V) return;
    float w0 = wv2[0], w1c = wv2[1], w2c = wv2[2], b = bv2[0];

    int myidx = nb2[v * NNB + c];
    const __nv_bfloat16* f1 = (const __nv_bfloat16*)g_f1b;
    float g[32];
#pragma unroll
    for (int j = 0; j < 32; j++) {
        int ij = __shfl_sync(0xffffffffu, myidx, j);
        g[j] = __bfloat162float(f1[ij * 32 + c]);
    }
    float acc = 0.f;
#pragma unroll
    for (int j = 0; j < 32; j++) {
        float gm = (j > 0)  ? g[j - 1] : 0.f;
        float gp = (j < 31) ? g[j + 1] : 0.f;
        acc += fmaxf(fmaf(w0, gm, fmaf(w1c, g[j], fmaf(w2c, gp, b))), 0.f);
    }
    float h2 = acc * (1.f / 32.f);
    g_h2b[v * 32 + c] = __bfloat16_as_ushort(__float2bfloat16(h2));
}

// --------------------------- Kpack: fold w2 into wfc, pack bf16 frags ------
// Wcomb[K=k3*32+ch][n] = sum_o w2[o,ch,k3]*wfc[n,o]; stored as mma B fragments:
// word(idx) for idx = s*4096 + g*64 + h*32 + l:
//   k2 = 8s+4h+(l&3), n = 8g+(l>>2); word = bf16(Wc[2k2][n]) | bf16(Wc[2k2+1][n])<<16
__global__ void k_pack(const float* __restrict__ w2, const float* __restrict__ wfc,
                       const float* __restrict__ b2, const float* __restrict__ bfc) {
    int blk = blockIdx.x;
    int tid = threadIdx.x;
    if (blk < 48) {
        int idx = blk * 512 + tid;
        int l = idx & 31;
        int h = (idx >> 5) & 1;
        int g = (idx >> 6) & 63;
        int s = idx >> 12;
        int k2 = 8 * s + 4 * h + (l & 3);
        int n  = 8 * g + (l >> 2);
        float v[2];
#pragma unroll
        for (int q = 0; q < 2; q++) {
            int K  = 2 * k2 + q;
            int k3 = K >> 5;
            int ch = K & 31;
            float sacc = 0.f;
#pragma unroll
            for (int o = 0; o < 64; o++)
                sacc = fmaf(w2[o * 96 + ch * 3 + k3], wfc[n * 64 + o], sacc);
            v[q] = sacc;
        }
        __nv_bfloat162 t = __floats2bfloat162_rn(v[0], v[1]);
        g_Wcb2[idx] = *(unsigned*)&t;
    } else {
        int p = tid;
        float s = bfc[p];
#pragma unroll
        for (int o = 0; o < 64; o++)
            s = fmaf(b2[o], wfc[p * 64 + o], s);
        g_bc[p] = s;
    }
}

// --------------------------- K4: tensor-core GEMM + bias + softmax ---------
// CTA: 256 threads = 8 warps, 64 vertices x 512 cols. Warp w owns cols
// [w*64, w*64+64). A panel [64 x 96] bf16 in smem (stride 104 -> conflict-free
// frag LDS). mma.sync.m16n8k16 row.col f32.bf16: 4 m-tiles x 8 n-tiles x 6 k.
__global__ void __launch_bounds__(256, 1)
k_out(float* __restrict__ out, int V) {
    __shared__ unsigned short As[64 * 104];
    __shared__ float redm[64][9];
    __shared__ float reds[64][9];
    int tid = threadIdx.x;
    int wp  = tid >> 5;
    int l   = tid & 31;
    int v0  = blockIdx.x * 64;

    // Build A panel (bf16 passthrough): As[v*104+K] = h2b[v0+v-1+k3][ch]
    for (int i = tid; i < 64 * 96; i += 256) {
        int v  = i / 96;
        int K  = i % 96;
        int k3 = K >> 5;
        int ch = K & 31;
        int row = v0 + v - 1 + k3;
        unsigned short val = (row >= 0 && row < V) ? g_h2b[row * 32 + ch]
                                                   : (unsigned short)0;
        As[v * 104 + K] = val;
    }
    __syncthreads();

    float acc[4][8][4];
#pragma unroll
    for (int m = 0; m < 4; m++)
#pragma unroll
        for (int nt = 0; nt < 8; nt++)
#pragma unroll
            for (int q = 0; q < 4; q++) acc[m][nt][q] = 0.f;

    int lq = l >> 2;        // 0..7
    int lr = l & 3;         // 0..3

#pragma unroll
    for (int s = 0; s < 6; s++) {
        // A fragments: 4 m-tiles x 4 regs
        unsigned a[4][4];
#pragma unroll
        for (int m = 0; m < 4; m++) {
            int r0 = (m * 16 + lq) * 104 + s * 16 + lr * 2;
            a[m][0] = *(const unsigned*)&As[r0];
            a[m][1] = *(const unsigned*)&As[r0 + 8 * 104];
            a[m][2] = *(const unsigned*)&As[r0 + 8];
            a[m][3] = *(const unsigned*)&As[r0 + 8 * 104 + 8];
        }
#pragma unroll
        for (int nt = 0; nt < 8; nt++) {
            int gg = wp * 8 + nt;
            unsigned b0 = g_Wcb2[((s * 64 + gg) * 2 + 0) * 32 + l];
            unsigned b1 = g_Wcb2[((s * 64 + gg) * 2 + 1) * 32 + l];
#pragma unroll
            for (int m = 0; m < 4; m++) {
                asm volatile(
                    "mma.sync.aligned.m16n8k16.row.col.f32.bf16.bf16.f32 "
                    "{%0,%1,%2,%3}, {%4,%5,%6,%7}, {%8,%9}, {%0,%1,%2,%3};"
                    : "+f"(acc[m][nt][0]), "+f"(acc[m][nt][1]),
                      "+f"(acc[m][nt][2]), "+f"(acc[m][nt][3])
                    : "r"(a[m][0]), "r"(a[m][1]), "r"(a[m][2]), "r"(a[m][3]),
                      "r"(b0), "r"(b1));
            }
        }
    }

    // bias: cols w*64 + nt*8 + lr*2 (+1); rows (c0,c1)=lq, (c2,c3)=lq+8
    float2 bb[8];
#pragma unroll
    for (int nt = 0; nt < 8; nt++)
        bb[nt] = *(const float2*)&g_bc[wp * 64 + nt * 8 + lr * 2];
#pragma unroll
    for (int m = 0; m < 4; m++)
#pragma unroll
        for (int nt = 0; nt < 8; nt++) {
            acc[m][nt][0] += bb[nt].x;
            acc[m][nt][1] += bb[nt].y;
            acc[m][nt][2] += bb[nt].x;
            acc[m][nt][3] += bb[nt].y;
        }

    // ---- softmax phase 1: per-warp row max -> smem ----
#pragma unroll
    for (int m = 0; m < 4; m++)
#pragma unroll
        for (int hf = 0; hf < 2; hf++) {
            float lm = -CUDART_INF_F;
#pragma unroll
            for (int nt = 0; nt < 8; nt++)
                lm = fmaxf(lm, fmaxf(acc[m][nt][hf * 2], acc[m][nt][hf * 2 + 1]));
            lm = fmaxf(lm, __shfl_xor_sync(0xffffffffu, lm, 1));
            lm = fmaxf(lm, __shfl_xor_sync(0xffffffffu, lm, 2));
            int r = m * 16 + hf * 8 + lq;
            if (lr == 0) redm[r][wp] = lm;
        }
    __syncthreads();

    // ---- phase 2: global max, exp, per-warp sum -> smem ----
#pragma unroll
    for (int m = 0; m < 4; m++)
#pragma unroll
        for (int hf = 0; hf < 2; hf++) {
            int r = m * 16 + hf * 8 + lq;
            float mm = redm[r][0];
#pragma unroll
            for (int j = 1; j < 8; j++) mm = fmaxf(mm, redm[r][j]);
            float ls = 0.f;
#pragma unroll
            for (int nt = 0; nt < 8; nt++) {
                float e0 = __expf(acc[m][nt][hf * 2]     - mm);
                float e1 = __expf(acc[m][nt][hf * 2 + 1] - mm);
                acc[m][nt][hf * 2]     = e0;
                acc[m][nt][hf * 2 + 1] = e1;
                ls += e0 + e1;
            }
            ls += __shfl_xor_sync(0xffffffffu, ls, 1);
            ls += __shfl_xor_sync(0xffffffffu, ls, 2);
            if (lr == 0) reds[r][wp] = ls;
        }
    __syncthreads();

    // ---- phase 3: normalize + store ----
#pragma unroll
    for (int m = 0; m < 4; m++)
#pragma unroll
        for (int hf = 0; hf < 2; hf++) {
            int r = m * 16 + hf * 8 + lq;
            float S = reds[r][0];
#pragma unroll
            for (int j = 1; j < 8; j++) S += reds[r][j];
            float inv = __fdividef(1.f, S);
            int v = v0 + r;
            if (v < V) {
                float* orow = out + (size_t)v * 512 + wp * 64 + lr * 2;
#pragma unroll
                for (int nt = 0; nt < 8; nt++) {
                    float2 o;
                    o.x = acc[m][nt][hf * 2]     * inv;
                    o.y = acc[m][nt][hf * 2 + 1] * inv;
                    *(float2*)(orow + nt * 8) = o;
                }
            }
        }
}

// ---------------------------------------------------------------------------
extern "C" void kernel_launch(void* const* d_in, const int* in_sizes, int n_in,
                              void* d_out, int out_size) {
    const float* vp  = (const float*)d_in[0];
    const int*   nb1 = (const int*)  d_in[1];
    const int*   nb2 = (const int*)  d_in[2];
    const float* wv1 = (const float*)d_in[3];
    const float* bv1 = (const float*)d_in[4];
    const float* w1  = (const float*)d_in[5];
    const float* b1  = (const float*)d_in[6];
    const float* wv2 = (const float*)d_in[7];
    const float* bv2 = (const float*)d_in[8];
    const float* w2  = (const float*)d_in[9];
    const float* b2  = (const float*)d_in[10];
    const float* wfc = (const float*)d_in[11];
    const float* bfc = (const float*)d_in[12];
    float* out = (float*)d_out;

    int V = in_sizes[0];
    if (V > V_MAX) V = V_MAX;

    int t32   = V * 32;
    int nblk  = (t32 + 255) / 256;

    k_pack<<<49, 512>>>(w2, wfc, b2, bfc);
    k_h  <<<nblk, 256>>>(vp, nb1, wv1, bv1, V);
    k_f1 <<<nblk, 256>>>(w1, b1, V);
    k_h2 <<<nblk, 256>>>(nb2, wv2, bv2, V);
    k_out<<<(V + 63) / 64, 256>>>(out, V);
}

// round 16
// speedup vs baseline: 1.5168x; 1.5168x over previous
#include <cuda_runtime.h>
#include <cuda_bf16.h>
#include <math_constants.h>

// ---------------------------------------------------------------------------
// CNNTest: graph conv (1->32) -> graph conv (32->64) -> FC(64->512) -> softmax
// V = 100000, N = 32 neighbors.
//
// R14 (resubmitted R16; repeated infra timeouts): revert R13's bf16
// intermediates (k_h2 is issue/latency-bound, NOT BW-bound; bf16 regressed it
// 44.9->75.6us). Base = R11 (205.8us) plus:
//   - k_h2: two-half neighbor buffer (peak regs ~40) + launch_bounds(256,6)
//     -> occupancy 52% -> ~62%.
//   - k_out/k_pack: B fragments repacked so (b0,b1) are lane-adjacent ->
//     one LDG.64 replaces two LDG.32 (96->48 B-loads per warp per CTA).
// ---------------------------------------------------------------------------

#define V_MAX 100352
#define NNB   32

__device__ float g_h [V_MAX];
__device__ float g_f1[V_MAX * 32];
__device__ float g_h2[V_MAX * 32];
__device__ unsigned g_Wcb2[6 * 64 * 32 * 2];   // [kstep][ntile][lane][b0/b1] bf16x2
__device__ float g_bc[512];

// --------------------------- K1: first graph conv (to scalar h) ------------
__global__ void k_h(const float* __restrict__ vp, const int* __restrict__ nb1,
                    const float* __restrict__ wv1, const float* __restrict__ bv1,
                    int V) {
    int t = blockIdx.x * blockDim.x + threadIdx.x;
    int v = t >> 5;
    int j = t & 31;
    if (v >= V) return;
    float w0 = wv1[0], w1c = wv1[1], w2c = wv1[2], b = bv1[0];

    int   idx = nb1[v * NNB + j];
    float g   = vp[idx];
    float gm  = __shfl_up_sync(0xffffffffu, g, 1);
    float gp  = __shfl_down_sync(0xffffffffu, g, 1);
    if (j == 0)  gm = 0.f;
    if (j == 31) gp = 0.f;
    float c = fmaf(w0, gm, fmaf(w1c, g, fmaf(w2c, gp, b)));
    float r = fmaxf(c, 0.f);
#pragma unroll
    for (int s = 16; s > 0; s >>= 1)
        r += __shfl_xor_sync(0xffffffffu, r, s);
    if (j == 0) g_h[v] = r * (1.f / 32.f);
}

// --------------------------- K2: vertex conv 1 -> 32 channels --------------
__global__ void k_f1(const float* __restrict__ w1, const float* __restrict__ b1,
                     int V) {
    int t = blockIdx.x * blockDim.x + threadIdx.x;
    if (t >= V * 32) return;
    int v = t >> 5;
    int o = t & 31;
    float hm = (v > 0)     ? g_h[v - 1] : 0.f;
    float h0 = g_h[v];
    float hp = (v < V - 1) ? g_h[v + 1] : 0.f;
    g_f1[t] = fmaf(hm, w1[o * 3 + 0],
              fmaf(h0, w1[o * 3 + 1],
              fmaf(hp, w1[o * 3 + 2], b1[o])));
}

// --------------------------- K3: second graph conv (neighbor axis) ---------
// One warp per vertex, lane = channel. Issue/latency-bound: two-half
// neighbor buffer trims peak registers; launch_bounds lifts occupancy.
__global__ void __launch_bounds__(256, 6)
k_h2(const int* __restrict__ nb2,
     const float* __restrict__ wv2, const float* __restrict__ bv2,
     int V) {
    int t = blockIdx.x * blockDim.x + threadIdx.x;
    int v = t >> 5;
    int c = t & 31;
    if (v >= V) return;
    float w0 = wv2[0], w1c = wv2[1], w2c = wv2[2], b = bv2[0];

    int myidx = nb2[v * NNB + c];

    // ---- first half: j = 0..15 needs g[0..16] ----
    float ga[17];
#pragma unroll
    for (int j = 0; j < 17; j++) {
        int ij = __shfl_sync(0xffffffffu, myidx, j);
        ga[j] = g_f1[ij * 32 + c];
    }
    float acc = fmaxf(fmaf(w1c, ga[0], fmaf(w2c, ga[1], b)), 0.f);  // j=0, gm=0
#pragma unroll
    for (int j = 1; j < 16; j++)
        acc += fmaxf(fmaf(w0, ga[j - 1],
                     fmaf(w1c, ga[j],
                     fmaf(w2c, ga[j + 1], b))), 0.f);

    // ---- second half: j = 16..31 needs g[15..31] ----
    float gb[17];
    gb[0] = ga[15];
    gb[1] = ga[16];
#pragma unroll
    for (int j = 17; j < 32; j++) {
        int ij = __shfl_sync(0xffffffffu, myidx, j);
        gb[j - 15] = g_f1[ij * 32 + c];
    }
#pragma unroll
    for (int j = 16; j < 31; j++) {
        int i = j - 15;   // 1..15
        acc += fmaxf(fmaf(w0, gb[i - 1],
                     fmaf(w1c, gb[i],
                     fmaf(w2c, gb[i + 1], b))), 0.f);
    }
    acc += fmaxf(fmaf(w0, gb[15], fmaf(w1c, gb[16], b)), 0.f);      // j=31, gp=0

    g_h2[v * 32 + c] = acc * (1.f / 32.f);
}

// --------------------------- Kpack: fold w2 into wfc, pack bf16 frags ------
// Wcomb[K=k3*32+ch][n] = sum_o w2[o,ch,k3]*wfc[n,o]; stored as mma B frags,
// (b0,b1) lane-adjacent: idx = ((s*64+g)*32+l)*2 + h,
//   k2 = 8s+4h+(l&3), n = 8g+(l>>2);
//   word = bf16(Wc[2k2][n]) | bf16(Wc[2k2+1][n])<<16
__global__ void k_pack(const float* __restrict__ w2, const float* __restrict__ wfc,
                       const float* __restrict__ b2, const float* __restrict__ bfc) {
    int blk = blockIdx.x;
    int tid = threadIdx.x;
    if (blk < 48) {
        int idx = blk * 512 + tid;
        int h = idx & 1;
        int l = (idx >> 1) & 31;
        int g = (idx >> 6) & 63;
        int s = idx >> 12;
        int k2 = 8 * s + 4 * h + (l & 3);
        int n  = 8 * g + (l >> 2);
        float v[2];
#pragma unroll
        for (int q = 0; q < 2; q++) {
            int K  = 2 * k2 + q;
            int k3 = K >> 5;
            int ch = K & 31;
            float sacc = 0.f;
#pragma unroll
            for (int o = 0; o < 64; o++)
                sacc = fmaf(w2[o * 96 + ch * 3 + k3], wfc[n * 64 + o], sacc);
            v[q] = sacc;
        }
        __nv_bfloat162 tt = __floats2bfloat162_rn(v[0], v[1]);
        g_Wcb2[idx] = *(unsigned*)&tt;
    } else {
        int p = tid;
        float s = bfc[p];
#pragma unroll
        for (int o = 0; o < 64; o++)
            s = fmaf(b2[o], wfc[p * 64 + o], s);
        g_bc[p] = s;
    }
}

// --------------------------- K4: tensor-core GEMM + bias + softmax ---------
// CTA: 256 threads = 8 warps, 64 vertices x 512 cols. Warp w owns cols
// [w*64, w*64+64). A panel [64 x 96] bf16 in smem (stride 104 -> conflict-free
// frag LDS). mma.sync.m16n8k16 row.col f32.bf16: 4 m-tiles x 8 n-tiles x 6 k.
// B fragment pairs loaded as single LDG.64 per (s,nt).
__global__ void __launch_bounds__(256, 1)
k_out(float* __restrict__ out, int V) {
    __shared__ unsigned short As[64 * 104];
    __shared__ float redm[64][9];
    __shared__ float reds[64][9];
    int tid = threadIdx.x;
    int wp  = tid >> 5;
    int l   = tid & 31;
    int v0  = blockIdx.x * 64;

    // Build A panel (bf16): As[v*104 + K] = h2[v0+v-1+k3][ch], K=k3*32+ch
    for (int i = tid; i < 64 * 96; i += 256) {
        int v  = i / 96;
        int K  = i % 96;
        int k3 = K >> 5;
        int ch = K & 31;
        int row = v0 + v - 1 + k3;
        float val = (row >= 0 && row < V) ? g_h2[row * 32 + ch] : 0.f;
        As[v * 104 + K] = __bfloat16_as_ushort(__float2bfloat16(val));
    }
    __syncthreads();

    float acc[4][8][4];
#pragma unroll
    for (int m = 0; m < 4; m++)
#pragma unroll
        for (int nt = 0; nt < 8; nt++)
#pragma unroll
            for (int q = 0; q < 4; q++) acc[m][nt][q] = 0.f;

    int lq = l >> 2;        // 0..7
    int lr = l & 3;         // 0..3

#pragma unroll
    for (int s = 0; s < 6; s++) {
        // A fragments: 4 m-tiles x 4 regs
        unsigned a[4][4];
#pragma unroll
        for (int m = 0; m < 4; m++) {
            int r0 = (m * 16 + lq) * 104 + s * 16 + lr * 2;
            a[m][0] = *(const unsigned*)&As[r0];
            a[m][1] = *(const unsigned*)&As[r0 + 8 * 104];
            a[m][2] = *(const unsigned*)&As[r0 + 8];
            a[m][3] = *(const unsigned*)&As[r0 + 8 * 104 + 8];
        }
#pragma unroll
        for (int nt = 0; nt < 8; nt++) {
            int gg = wp * 8 + nt;
            uint2 bv = *(const uint2*)&g_Wcb2[((s * 64 + gg) * 32 + l) * 2];
            unsigned b0 = bv.x;
            unsigned b1 = bv.y;
#pragma unroll
            for (int m = 0; m < 4; m++) {
                asm volatile(
                    "mma.sync.aligned.m16n8k16.row.col.f32.bf16.bf16.f32 "
                    "{%0,%1,%2,%3}, {%4,%5,%6,%7}, {%8,%9}, {%0,%1,%2,%3};"
                    : "+f"(acc[m][nt][0]), "+f"(acc[m][nt][1]),
                      "+f"(acc[m][nt][2]), "+f"(acc[m][nt][3])
                    : "r"(a[m][0]), "r"(a[m][1]), "r"(a[m][2]), "r"(a[m][3]),
                      "r"(b0), "r"(b1));
            }
        }
    }

    // bias: cols w*64 + nt*8 + lr*2 (+1); rows (c0,c1)=lq, (c2,c3)=lq+8
    float2 bb[8];
#pragma unroll
    for (int nt = 0; nt < 8; nt++)
        bb[nt] = *(const float2*)&g_bc[wp * 64 + nt * 8 + lr * 2];
#pragma unroll
    for (int m = 0; m < 4; m++)
#pragma unroll
        for (int nt = 0; nt < 8; nt++) {
            acc[m][nt][0] += bb[nt].x;
            acc[m][nt][1] += bb[nt].y;
            acc[m][nt][2] += bb[nt].x;
            acc[m][nt][3] += bb[nt].y;
        }

    // ---- softmax phase 1: per-warp row max -> smem ----
#pragma unroll
    for (int m = 0; m < 4; m++)
#pragma unroll
        for (int hf = 0; hf < 2; hf++) {
            float lm = -CUDART_INF_F;
#pragma unroll
            for (int nt = 0; nt < 8; nt++)
                lm = fmaxf(lm, fmaxf(acc[m][nt][hf * 2], acc[m][nt][hf * 2 + 1]));
            lm = fmaxf(lm, __shfl_xor_sync(0xffffffffu, lm, 1));
            lm = fmaxf(lm, __shfl_xor_sync(0xffffffffu, lm, 2));
            int r = m * 16 + hf * 8 + lq;
            if (lr == 0) redm[r][wp] = lm;
        }
    __syncthreads();

    // ---- phase 2: global max, exp, per-warp sum -> smem ----
#pragma unroll
    for (int m = 0; m < 4; m++)
#pragma unroll
        for (int hf = 0; hf < 2; hf++) {
            int r = m * 16 + hf * 8 + lq;
            float mm = redm[r][0];
#pragma unroll
            for (int j = 1; j < 8; j++) mm = fmaxf(mm, redm[r][j]);
            float ls = 0.f;
#pragma unroll
            for (int nt = 0; nt < 8; nt++) {
                float e0 = __expf(acc[m][nt][hf * 2]     - mm);
                float e1 = __expf(acc[m][nt][hf * 2 + 1] - mm);
                acc[m][nt][hf * 2]     = e0;
                acc[m][nt][hf * 2 + 1] = e1;
                ls += e0 + e1;
            }
            ls += __shfl_xor_sync(0xffffffffu, ls, 1);
            ls += __shfl_xor_sync(0xffffffffu, ls, 2);
            if (lr == 0) reds[r][wp] = ls;
        }
    __syncthreads();

    // ---- phase 3: normalize + store ----
#pragma unroll
    for (int m = 0; m < 4; m++)
#pragma unroll
        for (int hf = 0; hf < 2; hf++) {
            int r = m * 16 + hf * 8 + lq;
            float S = reds[r][0];
#pragma unroll
            for (int j = 1; j < 8; j++) S += reds[r][j];
            float inv = __fdividef(1.f, S);
            int v = v0 + r;
            if (v < V) {
                float* orow = out + (size_t)v * 512 + wp * 64 + lr * 2;
#pragma unroll
                for (int nt = 0; nt < 8; nt++) {
                    float2 o;
                    o.x = acc[m][nt][hf * 2]     * inv;
                    o.y = acc[m][nt][hf * 2 + 1] * inv;
                    *(float2*)(orow + nt * 8) = o;
                }
            }
        }
}

// ---------------------------------------------------------------------------
extern "C" void kernel_launch(void* const* d_in, const int* in_sizes, int n_in,
                              void* d_out, int out_size) {
    const float* vp  = (const float*)d_in[0];
    const int*   nb1 = (const int*)  d_in[1];
    const int*   nb2 = (const int*)  d_in[2];
    const float* wv1 = (const float*)d_in[3];
    const float* bv1 = (const float*)d_in[4];
    const float* w1  = (const float*)d_in[5];
    const float* b1  = (const float*)d_in[6];
    const float* wv2 = (const float*)d_in[7];
    const float* bv2 = (const float*)d_in[8];
    const float* w2  = (const float*)d_in[9];
    const float* b2  = (const float*)d_in[10];
    const float* wfc = (const float*)d_in[11];
    const float* bfc = (const float*)d_in[12];
    float* out = (float*)d_out;

    int V = in_sizes[0];
    if (V > V_MAX) V = V_MAX;

    int t32   = V * 32;
    int nblk  = (t32 + 255) / 256;

    k_pack<<<49, 512>>>(w2, wfc, b2, bfc);
    k_h  <<<nblk, 256>>>(vp, nb1, wv1, bv1, V);
    k_f1 <<<nblk, 256>>>(w1, b1, V);
    k_h2 <<<nblk, 256>>>(nb2, wv2, bv2, V);
    k_out<<<(V + 63) / 64, 256>>>(out, V);
}